// round 11
// baseline (speedup 1.0000x reference)
#include <cuda_runtime.h>
#include <math.h>

#define T      128
#define F      512
#define H      1024
#define RZ     1536
#define COLS   16            // columns per cluster
#define ROWS   768           // rows per CTA (rank-split)
#define NCL    64            // compute clusters
#define NCC    128           // compute CTAs
#define NPF    20            // L2-prefetch CTAs
#define NTH    384           // 256 consumers + 128 producers
#define D      4
#define LOOKAHEAD 12
#define SLOT_BYTES (ROWS * COLS * 4)   // 49152
#define SLOT_WORDS (ROWS * COLS)
#define STEP_LINES (RZ * H * 4 / 128)

__device__ float    g_h[T * H];
__device__ unsigned g_cnt[T];          // per-step, target NCL

__global__ void pg_init() {
    if (threadIdx.x < T) g_cnt[threadIdx.x] = 0u;
}

__device__ __forceinline__ unsigned ld_acq(const unsigned* p) {
    unsigned v;
    asm volatile("ld.global.acquire.gpu.u32 %0, [%1];" : "=r"(v) : "l"(p) : "memory");
    return v;
}
__device__ __forceinline__ void red_rel(unsigned* p, unsigned v) {
    asm volatile("red.release.gpu.global.add.u32 [%0], %1;" :: "l"(p), "r"(v) : "memory");
}
__device__ __forceinline__ void prefetch_l2(const void* p) {
    asm volatile("prefetch.global.L2 [%0];" :: "l"(p));
}
__device__ __forceinline__ void cp_async16(unsigned saddr, const void* gaddr) {
    asm volatile("cp.async.cg.shared.global [%0], [%1], 16;" :: "r"(saddr), "l"(gaddr));
}
__device__ __forceinline__ void cp_commit() { asm volatile("cp.async.commit_group;"); }
template<int N> __device__ __forceinline__ void cp_waitg() {
    asm volatile("cp.async.wait_group %0;" :: "n"(N));
}
__device__ __forceinline__ void bar1() {     // consumers only (256 threads)
    asm volatile("bar.sync 1, 256;" ::: "memory");
}
__device__ __forceinline__ unsigned mapa_r0(unsigned addr) {
    unsigned r;
    asm volatile("mapa.shared::cluster.u32 %0, %1, 0;" : "=r"(r) : "r"(addr));
    return r;
}
__device__ __forceinline__ void st_cluster_f32(unsigned addr, float v) {
    asm volatile("st.shared::cluster.f32 [%0], %1;" :: "r"(addr), "f"(v) : "memory");
}
__device__ __forceinline__ void mbar_arrive_rel_cluster(unsigned addr) {
    asm volatile("mbarrier.arrive.release.cluster.shared::cluster.b64 _, [%0];"
                 :: "r"(addr) : "memory");
}
__device__ __forceinline__ void mbar_wait_acq_cluster(unsigned addr, unsigned parity) {
    asm volatile(
        "{\n\t.reg .pred P1;\n\t"
        "WL_%=:\n\t"
        "mbarrier.try_wait.parity.acquire.cluster.shared::cta.b64 P1, [%0], %1, 0x989680;\n\t"
        "@P1 bra.uni WD_%=;\n\t"
        "bra.uni WL_%=;\n\t"
        "WD_%=:\n\t}"
        :: "r"(addr), "r"(parity) : "memory");
}

__global__ void __launch_bounds__(NTH, 1) __cluster_dims__(2, 1, 1)
pg_fused(
    const float* __restrict__ x,    // (1, T, F)
    const float* __restrict__ h0,   // (H,)
    const float* __restrict__ Ws,   // (T, RZ, H)
    const float* __restrict__ bs,   // (T, H)
    const float* __restrict__ Wo,   // (H, 2)
    const float* __restrict__ bo,   // (2,)
    float* __restrict__ out)        // [actors(2), h_final(H)]
{
    extern __shared__ char sm[];
    const int tid = threadIdx.x;

    // ================= L2-prefetch CTAs (clusters 64..73, both ranks) ============
    if (blockIdx.x >= NCC) {
        const int p  = blockIdx.x - NCC;
        const int gt = p * NTH + tid;
        for (int t = 0; t < T; ++t) {
            if (t >= LOOKAHEAD) {
                if (tid == 0) {
                    while (ld_acq(&g_cnt[t - LOOKAHEAD]) != (unsigned)NCL) { }
                }
                __syncthreads();
            }
            const char* base = (const char*)(Ws + (size_t)t * RZ * H);
            for (int line = gt; line < STEP_LINES; line += NPF * NTH)
                prefetch_l2(base + (size_t)line * 128);
        }
        return;
    }

    // ================= compute CTAs =================
    float* s_w    = (float*)sm;                          // D x 48KB tiles
    float* s_red  = (float*)(sm + D * SLOT_BYTES);       // 128 floats
    float* s_part = s_red + 128;                         // 16 floats (rank0 inbox)
    unsigned long long* s_mb = (unsigned long long*)(s_part + 16);  // mbarrier
    int*   s_full = (int*)(s_mb + 1);                    // D
    volatile int* s_consumed = (volatile int*)(s_full + D);

    const int cl   = blockIdx.x >> 1;                    // cluster id 0..63
    const int rank = blockIdx.x & 1;
    unsigned sbase = (unsigned)__cvta_generic_to_shared(s_w);
    unsigned pbase = (unsigned)__cvta_generic_to_shared(s_part);
    unsigned mbase = (unsigned)__cvta_generic_to_shared(s_mb);

    if (tid == 0) {
        for (int i = 0; i < D; ++i) s_full[i] = 0;
        *s_consumed = 0;
        if (rank == 0)
            asm volatile("mbarrier.init.shared.b64 [%0], 16;" :: "r"(mbase) : "memory");
    }
    __syncthreads();
    // cluster-wide: mbarrier visible before any remote arrive
    asm volatile("barrier.cluster.arrive.aligned;" ::: "memory");
    asm volatile("barrier.cluster.wait.aligned;" ::: "memory");

    if (tid >= 256) {
        // ---------------- producers: stream 768x16 tiles ----------------
        const int pt = tid - 256;                        // 0..127
        const float* gcols = Ws + (size_t)rank * ROWS * H + (size_t)cl * COLS;
        for (int t = 0; t < T; ++t) {
            while (*s_consumed < t - (D - 1)) { }
            unsigned sb = sbase + (unsigned)(t % D) * SLOT_BYTES;
            const float* gb = gcols + (size_t)t * RZ * H;
#pragma unroll
            for (int i = 0; i < 24; ++i) {
                int n   = i * 128 + pt;                  // 0..3071
                int row = n >> 2;
                int seg = n & 3;
                cp_async16(sb + (unsigned)(row * 64 + seg * 16),
                           (const void*)(gb + (size_t)row * H + seg * 4));
            }
            cp_commit();
            if (t >= 2) {
                cp_waitg<2>();
                __threadfence_block();
                atomicAdd(&s_full[(t - 2) % D], 1);
            }
        }
        cp_waitg<1>(); __threadfence_block(); atomicAdd(&s_full[(T - 2) % D], 1);
        cp_waitg<0>(); __threadfence_block(); atomicAdd(&s_full[(T - 1) % D], 1);
    } else {
        // ---------------- consumers ----------------
        const int w  = tid >> 5, l = tid & 31;
        const int c4 = l & 3;                            // float4 index (4 cols)
        const int rl = l >> 2;                           // row lane 0..7
        // number of i-iterations whose rows are x-rows (rank0 only)
        const int nx = (rank == 0) ? ((w < 5) ? 12 : (w == 5 ? 4 : 0)) : 0;

        for (int t = 0; t < T; ++t) {
            const int slot = t % D;
            float bval = 0.f;
            if (rank == 0 && tid < COLS) bval = __ldg(&bs[t * H + cl * COLS + tid]);

            // ---- tile ready? ----
            if (tid == 0) {
                while (((volatile int*)s_full)[slot] != 128) { }
            }
            bar1();

            const float* wslot = s_w + slot * SLOT_WORDS;
            float4 wv[12];
            float a0 = 0.f, a1 = 0.f, a2 = 0.f, a3 = 0.f;
#pragma unroll
            for (int i = 0; i < 12; ++i) {
                int row = w * 96 + rl + 8 * i;
                wv[i] = *(const float4*)(wslot + row * COLS + c4 * 4);
            }
            // ---- x-part FMAs (before detect; hides the poll) ----
#pragma unroll
            for (int i = 0; i < 12; ++i) {
                if (i < nx) {
                    int row = w * 96 + rl + 8 * i;
                    float zv = __ldg(&x[t * F + row]);
                    a0 = fmaf(zv, wv[i].x, a0); a1 = fmaf(zv, wv[i].y, a1);
                    a2 = fmaf(zv, wv[i].z, a2); a3 = fmaf(zv, wv[i].w, a3);
                }
            }

            // ---- acquire h_{t-1} ----
            if (tid == 0 && t > 0) {
                while (ld_acq(&g_cnt[t - 1]) != (unsigned)NCL) { }
            }
            bar1();

            const float* hp = (t == 0) ? h0 : (g_h + (size_t)(t - 1) * H);
            const int hoff = rank * ROWS - F;            // row -> h index
#pragma unroll
            for (int i = 0; i < 12; ++i) {
                if (i >= nx) {
                    int row = w * 96 + rl + 8 * i;
                    float zv = hp[row + hoff];
                    a0 = fmaf(zv, wv[i].x, a0); a1 = fmaf(zv, wv[i].y, a1);
                    a2 = fmaf(zv, wv[i].z, a2); a3 = fmaf(zv, wv[i].w, a3);
                }
            }

            // ---- reduce over the 8 row-lanes (same c4) ----
#pragma unroll
            for (int off = 4; off <= 16; off <<= 1) {
                a0 += __shfl_xor_sync(0xffffffffu, a0, off);
                a1 += __shfl_xor_sync(0xffffffffu, a1, off);
                a2 += __shfl_xor_sync(0xffffffffu, a2, off);
                a3 += __shfl_xor_sync(0xffffffffu, a3, off);
            }
            if (l < 4)
                *(float4*)(s_red + w * COLS + l * 4) = make_float4(a0, a1, a2, a3);
            bar1();                                      // slot fully consumed

            if (tid == 0) {                              // recycle slot
                s_full[slot] = 0;
                __threadfence_block();
                *s_consumed = t + 1;
            }

            if (rank == 1) {
                // ship 16 partials to rank0; per-thread release-arrive
                if (tid < COLS) {
                    float s = 0.f;
#pragma unroll
                    for (int ww = 0; ww < 8; ++ww) s += s_red[ww * COLS + tid];
                    st_cluster_f32(mapa_r0(pbase + tid * 4), s);
                    mbar_arrive_rel_cluster(mapa_r0(mbase));
                }
            } else {
                if (tid < COLS) {
                    mbar_wait_acq_cluster(mbase, (unsigned)(t & 1));
                    float s = bval + s_part[tid];
#pragma unroll
                    for (int ww = 0; ww < 8; ++ww) s += s_red[ww * COLS + tid];
                    float hv = tanhf(s);
                    int col = cl * COLS + tid;
                    g_h[(size_t)t * H + col] = hv;
                    if (t == T - 1) out[2 + col] = hv;
                }
                __syncwarp(0xffffffffu);
                if (tid == 0) red_rel(&g_cnt[t], 1u);
            }
        }

        // ---------------- actor head (blockIdx 0) ----------------
        if (cl == 0 && rank == 0) {
            if (tid == 0) while (ld_acq(&g_cnt[T - 1]) != (unsigned)NCL) { }
            bar1();
            const float* hf = g_h + (size_t)(T - 1) * H;
            float r0 = 0.f, r1 = 0.f;
            for (int i = tid; i < H; i += 256) {
                float hv = hf[i];
                r0 = fmaf(hv, Wo[2 * i + 0], r0);
                r1 = fmaf(hv, Wo[2 * i + 1], r1);
            }
#pragma unroll
            for (int off = 16; off >= 1; off >>= 1) {
                r0 += __shfl_xor_sync(0xffffffffu, r0, off);
                r1 += __shfl_xor_sync(0xffffffffu, r1, off);
            }
            if (l == 0) { s_red[w] = r0; s_red[8 + w] = r1; }
            bar1();
            if (tid == 0) {
                float s0 = 0.f, s1 = 0.f;
#pragma unroll
                for (int ww = 0; ww < 8; ++ww) { s0 += s_red[ww]; s1 += s_red[8 + ww]; }
                out[0] = s0 + bo[0];
                out[1] = s1 + bo[1];
            }
        }
    }

    // cluster exit safety: peer DSMEM traffic must drain before either CTA exits
    asm volatile("barrier.cluster.arrive.aligned;" ::: "memory");
    asm volatile("barrier.cluster.wait.aligned;" ::: "memory");
}

extern "C" void kernel_launch(void* const* d_in, const int* in_sizes, int n_in,
                              void* d_out, int out_size) {
    const float* x  = (const float*)d_in[0];
    const float* h0 = (const float*)d_in[1];
    const float* Ws = (const float*)d_in[2];
    const float* bs = (const float*)d_in[3];
    const float* Wo = (const float*)d_in[4];
    const float* bo = (const float*)d_in[5];
    float* out = (float*)d_out;

    static bool attr_set = false;
    if (!attr_set) {
        cudaFuncSetAttribute(pg_fused, cudaFuncAttributeMaxDynamicSharedMemorySize,
                             D * SLOT_BYTES + 2048);
        attr_set = true;
    }

    pg_init<<<1, 128>>>();
    pg_fused<<<NCC + NPF, NTH, D * SLOT_BYTES + 2048>>>(x, h0, Ws, bs, Wo, bo, out);
}

// round 12
// speedup vs baseline: 1.0786x; 1.0786x over previous
#include <cuda_runtime.h>
#include <math.h>

#define T      128
#define F      512
#define H      1024
#define RZ     1536
#define CPB    8
#define NC     128           // compute CTAs
#define NPF    20            // L2-prefetch CTAs
#define NTH    384           // 256 consumers + 128 producers
#define D      4
#define LOOKAHEAD 12
#define SLOT_BYTES (RZ * CPB * 4)     // 49152
#define SLOT_WORDS (RZ * CPB)
#define STEP_LINES (RZ * H * 4 / 128)

__device__ float    g_h[T * H];
__device__ unsigned g_cnt[T];

__global__ void pg_init() {
    if (threadIdx.x < T) g_cnt[threadIdx.x] = 0u;
}

__device__ __forceinline__ unsigned ld_acq(const unsigned* p) {
    unsigned v;
    asm volatile("ld.global.acquire.gpu.u32 %0, [%1];" : "=r"(v) : "l"(p) : "memory");
    return v;
}
__device__ __forceinline__ void red_rel(unsigned* p, unsigned v) {
    asm volatile("red.release.gpu.global.add.u32 [%0], %1;" :: "l"(p), "r"(v) : "memory");
}
__device__ __forceinline__ void prefetch_l2(const void* p) {
    asm volatile("prefetch.global.L2 [%0];" :: "l"(p));
}
__device__ __forceinline__ void cp_async16(unsigned saddr, const void* gaddr) {
    asm volatile("cp.async.cg.shared.global [%0], [%1], 16;" :: "r"(saddr), "l"(gaddr));
}
__device__ __forceinline__ void cp_commit() { asm volatile("cp.async.commit_group;"); }
template<int N> __device__ __forceinline__ void cp_waitg() {
    asm volatile("cp.async.wait_group %0;" :: "n"(N));
}
__device__ __forceinline__ void bar1() {     // consumers only (256 threads)
    asm volatile("bar.sync 1, 256;" ::: "memory");
}

__global__ void __launch_bounds__(NTH, 1) pg_fused(
    const float* __restrict__ x,    // (1, T, F)
    const float* __restrict__ h0,   // (H,)
    const float* __restrict__ Ws,   // (T, RZ, H)
    const float* __restrict__ bs,   // (T, H)
    const float* __restrict__ Wo,   // (H, 2)
    const float* __restrict__ bo,   // (2,)
    float* __restrict__ out)        // [actors(2), h_final(H)]
{
    extern __shared__ char sm[];
    const int tid = threadIdx.x;

    // ================= L2-prefetch CTAs =================
    if (blockIdx.x >= NC) {
        const int p  = blockIdx.x - NC;
        const int gt = p * NTH + tid;
        for (int t = 0; t < T; ++t) {
            if (t >= LOOKAHEAD) {
                if (tid == 0) {
                    while (ld_acq(&g_cnt[t - LOOKAHEAD]) != (unsigned)NC) { }
                }
                __syncthreads();
            }
            const char* base = (const char*)(Ws + (size_t)t * RZ * H);
            for (int line = gt; line < STEP_LINES; line += NPF * NTH)
                prefetch_l2(base + (size_t)line * 128);
        }
        return;
    }

    // ================= compute CTAs =================
    float* s_w    = (float*)sm;                        // D x 48KB z-tiles
    float* s_red  = (float*)(sm + D * SLOT_BYTES);     // 64
    int*   s_full = (int*)(s_red + 64);                // D
    volatile int* s_consumed = (volatile int*)(s_full + D);
    volatile int* s_go       = (volatile int*)(s_full + D + 1);  // pacing flag

    const int cg = blockIdx.x;
    unsigned sbase = (unsigned)__cvta_generic_to_shared(s_w);

    if (tid == 0) {
        for (int i = 0; i < D; ++i) s_full[i] = 0;
        *s_consumed = 0;
        *s_go = -1;
    }
    __syncthreads();

    if (tid >= 256) {
        // ---------------- producers: gated burst streaming ----------------
        const int pt = tid - 256;                      // 0..127
        const int pl = pt & 31;                        // lane within producer warp
        const float* gcols = Ws + (size_t)cg * CPB;
        for (int t = 0; t < T; ++t) {
            if (pl == 0) {
                while (*s_consumed < t - (D - 1)) { }
                // pacing gate: issue tile t only once consumers are in step t-3's
                // compute window (go >= t-3). Correctness-neutral (pure pacing).
                while (*s_go < t - 3) { }
            }
            __syncwarp(0xffffffffu);
            unsigned sb = sbase + (unsigned)(t % D) * SLOT_BYTES;
            const float* gb = gcols + (size_t)t * RZ * H;
#pragma unroll
            for (int i = 0; i < 24; ++i) {
                int n   = i * 128 + pt;
                int row = n >> 1;
                int cc  = n & 1;
                unsigned soff = sb + (unsigned)(row * 32 + ((cc ^ ((row >> 2) & 1)) << 4));
                cp_async16(soff, (const void*)(gb + (size_t)row * H + cc * 4));
            }
            cp_commit();
            if (t >= 2) {
                cp_waitg<2>();
                __threadfence_block();
                atomicAdd(&s_full[(t - 2) % D], 1);
            }
        }
        cp_waitg<1>(); __threadfence_block(); atomicAdd(&s_full[(T - 2) % D], 1);
        cp_waitg<0>(); __threadfence_block(); atomicAdd(&s_full[(T - 1) % D], 1);
    } else {
        // ---------------- consumers ----------------
        const int w = tid >> 5, l = tid & 31;
        for (int t = 0; t < T; ++t) {
            const int slot = t % D;
            float bval = 0.f;
            if (tid < 8) bval = __ldg(&bs[t * H + cg * CPB + tid]);

            // ---- tile ready? ----
            if (tid == 0) {
                while (((volatile int*)s_full)[slot] != 128) { }
            }
            bar1();
            if (t == 0 && tid == 0) *s_go = 0;        // open gate (no detect at t=0)

            const float* wslot = s_w + slot * SLOT_WORDS;
            float acc[8];
#pragma unroll
            for (int j = 0; j < 8; ++j) acc[j] = 0.f;

            // ---- x-part (rows 0..511): hides the detect below ----
#pragma unroll
            for (int i = 0; i < 2; ++i) {
                int r = w * 64 + i * 32 + l;
                float zv = __ldg(&x[t * F + r]);
                int sw = (r >> 2) & 1;
                float4 c0 = *(const float4*)(wslot + r * 8 + sw * 4);
                float4 c1 = *(const float4*)(wslot + r * 8 + (sw ^ 1) * 4);
                acc[0] = fmaf(zv, c0.x, acc[0]); acc[1] = fmaf(zv, c0.y, acc[1]);
                acc[2] = fmaf(zv, c0.z, acc[2]); acc[3] = fmaf(zv, c0.w, acc[3]);
                acc[4] = fmaf(zv, c1.x, acc[4]); acc[5] = fmaf(zv, c1.y, acc[5]);
                acc[6] = fmaf(zv, c1.z, acc[6]); acc[7] = fmaf(zv, c1.w, acc[7]);
            }

            // ---- acquire h_{t-1} ----
            if (tid == 0 && t > 0) {
                while (ld_acq(&g_cnt[t - 1]) != (unsigned)NC) { }
            }
            bar1();
            if (t > 0 && tid == 0) *s_go = t;         // h-LDGs issuing now: release burst

            const float* hp = (t == 0) ? h0 : (g_h + (size_t)(t - 1) * H);
            float zv2[4];
#pragma unroll
            for (int i = 0; i < 4; ++i)                 // issue all 4 LDGs first
                zv2[i] = hp[w * 128 + i * 32 + l];
#pragma unroll
            for (int i = 0; i < 4; ++i) {
                int r = F + w * 128 + i * 32 + l;
                int sw = (r >> 2) & 1;
                float4 c0 = *(const float4*)(wslot + r * 8 + sw * 4);
                float4 c1 = *(const float4*)(wslot + r * 8 + (sw ^ 1) * 4);
                float zv = zv2[i];
                acc[0] = fmaf(zv, c0.x, acc[0]); acc[1] = fmaf(zv, c0.y, acc[1]);
                acc[2] = fmaf(zv, c0.z, acc[2]); acc[3] = fmaf(zv, c0.w, acc[3]);
                acc[4] = fmaf(zv, c1.x, acc[4]); acc[5] = fmaf(zv, c1.y, acc[5]);
                acc[6] = fmaf(zv, c1.z, acc[6]); acc[7] = fmaf(zv, c1.w, acc[7]);
            }

            // ---- reduce over 32 lanes per warp ----
#pragma unroll
            for (int off = 16; off >= 1; off >>= 1)
#pragma unroll
                for (int j = 0; j < 8; ++j)
                    acc[j] += __shfl_xor_sync(0xffffffffu, acc[j], off);
            if (l == 0) {
#pragma unroll
                for (int j = 0; j < 8; ++j) s_red[w * 8 + j] = acc[j];
            }
            bar1();                                   // slot fully consumed here

            if (tid == 0) {                           // recycle the slot
                s_full[slot] = 0;
                __threadfence_block();
                *s_consumed = t + 1;
            }
            // warp 0 finishes the step: combine, tanh, store, release
            if (tid < 8) {
                float s = bval;
#pragma unroll
                for (int ww = 0; ww < 8; ++ww) s += s_red[ww * 8 + tid];
                float hv = tanhf(s);
                int col = cg * CPB + tid;
                g_h[(size_t)t * H + col] = hv;
                if (t == T - 1) out[2 + col] = hv;
            }
            __syncwarp(0xffffffffu);                  // order stores before release
            if (tid == 0) red_rel(&g_cnt[t], 1u);     // ONE atomic per CTA
        }

        // ---------------- actor head (CTA 0) ----------------
        if (cg == 0) {
            if (tid == 0) while (ld_acq(&g_cnt[T - 1]) != (unsigned)NC) { }
            bar1();
            const float* hf = g_h + (size_t)(T - 1) * H;
            float r0 = 0.f, r1 = 0.f;
            for (int i = tid; i < H; i += 256) {
                float hv = hf[i];
                r0 = fmaf(hv, Wo[2 * i + 0], r0);
                r1 = fmaf(hv, Wo[2 * i + 1], r1);
            }
#pragma unroll
            for (int off = 16; off >= 1; off >>= 1) {
                r0 += __shfl_xor_sync(0xffffffffu, r0, off);
                r1 += __shfl_xor_sync(0xffffffffu, r1, off);
            }
            if (l == 0) { s_red[w] = r0; s_red[8 + w] = r1; }
            bar1();
            if (tid == 0) {
                float s0 = 0.f, s1 = 0.f;
#pragma unroll
                for (int ww = 0; ww < 8; ++ww) { s0 += s_red[ww]; s1 += s_red[8 + ww]; }
                out[0] = s0 + bo[0];
                out[1] = s1 + bo[1];
            }
        }
    }
}

extern "C" void kernel_launch(void* const* d_in, const int* in_sizes, int n_in,
                              void* d_out, int out_size) {
    const float* x  = (const float*)d_in[0];
    const float* h0 = (const float*)d_in[1];
    const float* Ws = (const float*)d_in[2];
    const float* bs = (const float*)d_in[3];
    const float* Wo = (const float*)d_in[4];
    const float* bo = (const float*)d_in[5];
    float* out = (float*)d_out;

    static bool attr_set = false;
    if (!attr_set) {
        cudaFuncSetAttribute(pg_fused, cudaFuncAttributeMaxDynamicSharedMemorySize,
                             D * SLOT_BYTES + 1024);
        attr_set = true;
    }

    pg_init<<<1, 128>>>();
    pg_fused<<<NC + NPF, NTH, D * SLOT_BYTES + 1024>>>(x, h0, Ws, bs, Wo, bo, out);
}

// round 13
// speedup vs baseline: 1.1427x; 1.0595x over previous
#include <cuda_runtime.h>
#include <math.h>

#define T      128
#define F      512
#define H      1024
#define RZ     1536
#define CPB    8
#define NC     128           // compute CTAs
#define NPF    20            // L2-prefetch CTAs
#define NTH    384           // 256 consumers + 128 producers
#define D      4
#define LOOKAHEAD 12
#define SLOT_BYTES (RZ * CPB * 4)     // 49152
#define SLOT_WORDS (RZ * CPB)
#define STEP_LINES (RZ * H * 4 / 128)

__device__ float    g_h[T * H];
__device__ unsigned g_cnt[T];

__global__ void pg_init() {
    if (threadIdx.x < T) g_cnt[threadIdx.x] = 0u;
}

__device__ __forceinline__ unsigned ld_acq(const unsigned* p) {
    unsigned v;
    asm volatile("ld.global.acquire.gpu.u32 %0, [%1];" : "=r"(v) : "l"(p) : "memory");
    return v;
}
__device__ __forceinline__ void red_rel(unsigned* p, unsigned v) {
    asm volatile("red.release.gpu.global.add.u32 [%0], %1;" :: "l"(p), "r"(v) : "memory");
}
__device__ __forceinline__ unsigned ld_acq_sh(unsigned a) {
    unsigned v;
    asm volatile("ld.acquire.cta.shared.u32 %0, [%1];" : "=r"(v) : "r"(a) : "memory");
    return v;
}
__device__ __forceinline__ float ld_acq_sh_f32(unsigned a) {
    float v;
    asm volatile("ld.acquire.cta.shared.f32 %0, [%1];" : "=f"(v) : "r"(a) : "memory");
    return v;
}
__device__ __forceinline__ void st_rel_sh(unsigned a, unsigned v) {
    asm volatile("st.release.cta.shared.u32 [%0], %1;" :: "r"(a), "r"(v) : "memory");
}
__device__ __forceinline__ void red_add_rel_sh(unsigned a, unsigned v) {
    asm volatile("red.add.release.cta.shared.u32 [%0], %1;" :: "r"(a), "r"(v) : "memory");
}
__device__ __forceinline__ unsigned atom_add_acqrel_sh(unsigned a, unsigned v) {
    unsigned old;
    asm volatile("atom.add.acq_rel.cta.shared.u32 %0, [%1], %2;"
                 : "=r"(old) : "r"(a), "r"(v) : "memory");
    return old;
}
__device__ __forceinline__ void prefetch_l2(const void* p) {
    asm volatile("prefetch.global.L2 [%0];" :: "l"(p));
}
__device__ __forceinline__ void cp_async16(unsigned saddr, const void* gaddr) {
    asm volatile("cp.async.cg.shared.global [%0], [%1], 16;" :: "r"(saddr), "l"(gaddr));
}
__device__ __forceinline__ void cp_commit() { asm volatile("cp.async.commit_group;"); }
template<int N> __device__ __forceinline__ void cp_waitg() {
    asm volatile("cp.async.wait_group %0;" :: "n"(N));
}
__device__ __forceinline__ void bar1() {     // consumers only (256 threads); OUTSIDE hot loop
    asm volatile("bar.sync 1, 256;" ::: "memory");
}

__global__ void __launch_bounds__(NTH, 1) pg_fused(
    const float* __restrict__ x,    // (1, T, F)
    const float* __restrict__ h0,   // (H,)
    const float* __restrict__ Ws,   // (T, RZ, H)
    const float* __restrict__ bs,   // (T, H)
    const float* __restrict__ Wo,   // (H, 2)
    const float* __restrict__ bo,   // (2,)
    float* __restrict__ out)        // [actors(2), h_final(H)]
{
    extern __shared__ char sm[];
    const int tid = threadIdx.x;

    // ================= L2-prefetch CTAs =================
    if (blockIdx.x >= NC) {
        const int p  = blockIdx.x - NC;
        const int gt = p * NTH + tid;
        for (int t = 0; t < T; ++t) {
            if (t >= LOOKAHEAD) {
                if (tid == 0) {
                    while (ld_acq(&g_cnt[t - LOOKAHEAD]) != (unsigned)NC) { }
                }
                __syncthreads();
            }
            const char* base = (const char*)(Ws + (size_t)t * RZ * H);
            for (int line = gt; line < STEP_LINES; line += NPF * NTH)
                prefetch_l2(base + (size_t)line * 128);
        }
        return;
    }

    // ================= compute CTAs =================
    float* s_w    = (float*)sm;                          // D x 48KB z-tiles
    float* s_red  = (float*)(sm + D * SLOT_BYTES);       // [2][64] parity buffers
    float* s_bias = s_red + 128;                         // [T][8] preloaded bias
    int*   s_full = (int*)(s_bias + T * CPB);            // D
    int*   s_consumed = s_full + D;
    int*   s_hgo  = s_consumed + 1;                      // monotonic h-ready step
    int*   s_done = s_hgo + 1;                           // [2] parity counters

    const int cg = blockIdx.x;
    unsigned sbase  = (unsigned)__cvta_generic_to_shared(s_w);
    unsigned redb   = (unsigned)__cvta_generic_to_shared(s_red);
    unsigned fullb  = (unsigned)__cvta_generic_to_shared(s_full);
    unsigned consb  = (unsigned)__cvta_generic_to_shared(s_consumed);
    unsigned hgob   = (unsigned)__cvta_generic_to_shared(s_hgo);
    unsigned doneb  = (unsigned)__cvta_generic_to_shared(s_done);

    if (tid == 0) {
        for (int i = 0; i < D; ++i) s_full[i] = 0;
        *s_consumed = 0;
        *s_hgo = 0;
        s_done[0] = 0; s_done[1] = 0;
    }
    __syncthreads();

    if (tid >= 256) {
        // ---------------- producers: stream full z-tiles (R7, release edge) ------
        const int pt = tid - 256;                      // 0..127
        const float* gcols = Ws + (size_t)cg * CPB;
        for (int t = 0; t < T; ++t) {
            while ((int)ld_acq_sh(consb) < t - (D - 1)) { }
            unsigned sb = sbase + (unsigned)(t % D) * SLOT_BYTES;
            const float* gb = gcols + (size_t)t * RZ * H;
#pragma unroll
            for (int i = 0; i < 24; ++i) {
                int n   = i * 128 + pt;
                int row = n >> 1;
                int cc  = n & 1;
                unsigned soff = sb + (unsigned)(row * 32 + ((cc ^ ((row >> 2) & 1)) << 4));
                cp_async16(soff, (const void*)(gb + (size_t)row * H + cc * 4));
            }
            cp_commit();
            if (t >= 2) {
                cp_waitg<2>();
                red_add_rel_sh(fullb + ((t - 2) % D) * 4, 1u);
            }
        }
        cp_waitg<1>(); red_add_rel_sh(fullb + ((T - 2) % D) * 4, 1u);
        cp_waitg<0>(); red_add_rel_sh(fullb + ((T - 1) % D) * 4, 1u);
    } else {
        // ---------------- consumers: barrier-free dataflow ----------------
        const int w = tid >> 5, l = tid & 31;

        // preload this CTA's bias column block (off critical path)
        for (int i = tid; i < T * CPB; i += 256) {
            int tt = i >> 3, j = i & 7;
            s_bias[i] = __ldg(&bs[tt * H + cg * CPB + j]);
        }
        bar1();                                          // one-time

        for (int t = 0; t < T; ++t) {
            const int slot = t % D;
            const int par  = t & 1;

            // ---- tile ready: per-warp acquire poll ----
            while (ld_acq_sh(fullb + slot * 4) != 128u) { }

            const float* wslot = s_w + slot * SLOT_WORDS;
            float acc[8];
#pragma unroll
            for (int j = 0; j < 8; ++j) acc[j] = 0.f;

            // ---- x-part (rows 0..511): overlaps h detect ----
#pragma unroll
            for (int i = 0; i < 2; ++i) {
                int r = w * 64 + i * 32 + l;
                float zv = __ldg(&x[t * F + r]);
                int sw = (r >> 2) & 1;
                float4 c0 = *(const float4*)(wslot + r * 8 + sw * 4);
                float4 c1 = *(const float4*)(wslot + r * 8 + (sw ^ 1) * 4);
                acc[0] = fmaf(zv, c0.x, acc[0]); acc[1] = fmaf(zv, c0.y, acc[1]);
                acc[2] = fmaf(zv, c0.z, acc[2]); acc[3] = fmaf(zv, c0.w, acc[3]);
                acc[4] = fmaf(zv, c1.x, acc[4]); acc[5] = fmaf(zv, c1.y, acc[5]);
                acc[6] = fmaf(zv, c1.z, acc[6]); acc[7] = fmaf(zv, c1.w, acc[7]);
            }

            // ---- h ready: warp0 polls global, relays via monotonic smem flag ----
            if (t > 0) {
                if (w == 0) {
                    while (ld_acq(&g_cnt[t - 1]) != (unsigned)NC) { }
                    __syncwarp(0xffffffffu);
                    if (l == 0) st_rel_sh(hgob, (unsigned)t);
                } else {
                    while ((int)ld_acq_sh(hgob) < t) { }
                }
            }

            const float* hp = (t == 0) ? h0 : (g_h + (size_t)(t - 1) * H);
            float zv2[4];
#pragma unroll
            for (int i = 0; i < 4; ++i)                 // issue all 4 LDGs first
                zv2[i] = hp[w * 128 + i * 32 + l];
#pragma unroll
            for (int i = 0; i < 4; ++i) {
                int r = F + w * 128 + i * 32 + l;
                int sw = (r >> 2) & 1;
                float4 c0 = *(const float4*)(wslot + r * 8 + sw * 4);
                float4 c1 = *(const float4*)(wslot + r * 8 + (sw ^ 1) * 4);
                float zv = zv2[i];
                acc[0] = fmaf(zv, c0.x, acc[0]); acc[1] = fmaf(zv, c0.y, acc[1]);
                acc[2] = fmaf(zv, c0.z, acc[2]); acc[3] = fmaf(zv, c0.w, acc[3]);
                acc[4] = fmaf(zv, c1.x, acc[4]); acc[5] = fmaf(zv, c1.y, acc[5]);
                acc[6] = fmaf(zv, c1.z, acc[6]); acc[7] = fmaf(zv, c1.w, acc[7]);
            }

            // ---- warp reduce (R7) ----
#pragma unroll
            for (int off = 16; off >= 1; off >>= 1)
#pragma unroll
                for (int j = 0; j < 8; ++j)
                    acc[j] += __shfl_xor_sync(0xffffffffu, acc[j], off);

            // ---- publish partials; LAST warp finishes the step ----
            unsigned old = 0;
            if (l == 0) {
#pragma unroll
                for (int j = 0; j < 8; ++j) s_red[par * 64 + w * 8 + j] = acc[j];
                old = atom_add_acqrel_sh(doneb + par * 4, 1u);
            }
            old = __shfl_sync(0xffffffffu, old, 0);

            if (old == 7u) {                             // last arriver publishes
                if (l < 8) {
                    float s = s_bias[t * 8 + l];
#pragma unroll
                    for (int ww = 0; ww < 8; ++ww)
                        s += ld_acq_sh_f32(redb + (par * 64 + ww * 8 + l) * 4);
                    float hv = tanhf(s);
                    int col = cg * CPB + l;
                    g_h[(size_t)t * H + col] = hv;
                    if (t == T - 1) out[2 + col] = hv;
                }
                __syncwarp(0xffffffffu);
                if (l == 0) {
                    s_done[par] = 0;                     // parity reuse at t+2 is
                    s_full[slot] = 0;                    // ordered via g_cnt chain
                    __threadfence_block();
                    *(volatile int*)s_consumed = t + 1;
                    red_rel(&g_cnt[t], 1u);
                }
            }
        }

        // ---------------- actor head (CTA 0) ----------------
        if (cg == 0) {
            while (ld_acq(&g_cnt[T - 1]) != (unsigned)NC) { }
            bar1();
            const float* hf = g_h + (size_t)(T - 1) * H;
            float r0 = 0.f, r1 = 0.f;
            for (int i = tid; i < H; i += 256) {
                float hv = hf[i];
                r0 = fmaf(hv, Wo[2 * i + 0], r0);
                r1 = fmaf(hv, Wo[2 * i + 1], r1);
            }
#pragma unroll
            for (int off = 16; off >= 1; off >>= 1) {
                r0 += __shfl_xor_sync(0xffffffffu, r0, off);
                r1 += __shfl_xor_sync(0xffffffffu, r1, off);
            }
            if (l == 0) { s_red[w] = r0; s_red[8 + w] = r1; }
            bar1();
            if (tid == 0) {
                float s0 = 0.f, s1 = 0.f;
#pragma unroll
                for (int ww = 0; ww < 8; ++ww) { s0 += s_red[ww]; s1 += s_red[8 + ww]; }
                out[0] = s0 + bo[0];
                out[1] = s1 + bo[1];
            }
        }
    }
}

extern "C" void kernel_launch(void* const* d_in, const int* in_sizes, int n_in,
                              void* d_out, int out_size) {
    const float* x  = (const float*)d_in[0];
    const float* h0 = (const float*)d_in[1];
    const float* Ws = (const float*)d_in[2];
    const float* bs = (const float*)d_in[3];
    const float* Wo = (const float*)d_in[4];
    const float* bo = (const float*)d_in[5];
    float* out = (float*)d_out;

    static bool attr_set = false;
    if (!attr_set) {
        cudaFuncSetAttribute(pg_fused, cudaFuncAttributeMaxDynamicSharedMemorySize,
                             D * SLOT_BYTES + 8192);
        attr_set = true;
    }

    pg_init<<<1, 128>>>();
    pg_fused<<<NC + NPF, NTH, D * SLOT_BYTES + 8192>>>(x, h0, Ws, bs, Wo, bo, out);
}